// round 6
// baseline (speedup 1.0000x reference)
#include <cuda_runtime.h>
#include <cuda_fp16.h>
#include <cstddef>
#include <cstdint>

#define N_VARS   4096
#define WIDTH    8192
#define N_LAYERS 12
#define BATCH    1024
#define THREADS  1024
#define BCH      8                          // batch rows per CTA (8 halves = 16B/node)
#define NPT      (WIDTH / THREADS)          // 8 nodes per thread
#define N_PAIRS  (N_LAYERS / 2)             // 6 fused product->sum stages

typedef unsigned int u32;

// Fused index tables: for pair p, node i:
//   s = children[2p+1][i];  (A,B) = children[2p][s.x];  (C,D) = children[2p][s.y]
// out[i] = buf[A]*buf[B] + buf[C]*buf[D]
__device__ int4 g_fused[N_PAIRS * WIDTH];

__global__ __launch_bounds__(256) void prep_kernel(const int2* __restrict__ children)
{
    const int idx = blockIdx.x * blockDim.x + threadIdx.x;
    const int p = idx >> 13;          // / WIDTH
    const int i = idx & (WIDTH - 1);
    const int2* ch_even = children + (size_t)(2 * p) * WIDTH;
    const int2 s = __ldg(&children[(size_t)(2 * p + 1) * WIDTH + i]);
    const int2 a = __ldg(&ch_even[s.x]);
    const int2 b = __ldg(&ch_even[s.y]);
    g_fused[idx] = make_int4(a.x, a.y, b.x, b.y);
}

__device__ __forceinline__ u32 h2_as_u32(__half2 h) { u32 r; __builtin_memcpy(&r, &h, 4); return r; }
__device__ __forceinline__ __half2 u32_as_h2(u32 u) { __half2 h; __builtin_memcpy(&h, &u, 4); return h; }

// r = x1*y1 + x2*y2 (half2 lanes), one rounding fewer via hfma2
__device__ __forceinline__ u32 fuse_u(u32 x1, u32 y1, u32 x2, u32 y2) {
    return h2_as_u32(__hfma2(u32_as_h2(x2), u32_as_h2(y2),
                             __hmul2(u32_as_h2(x1), u32_as_h2(y1))));
}

// One CTA (32 warps) per group of 8 batch rows; vals node-major as 8 halves
// (uint4) in 128KB SMEM. 6 fused product->sum stages: 4 random LDS.128 + 1
// hfma2 chain + 1 store per node. Stage 5 folds into the fp32 reduction.
__global__ __launch_bounds__(THREADS, 1) void wmc_kernel(
    const float* __restrict__ weights,
    const float* __restrict__ neg_weights,
    float* __restrict__ out)
{
    extern __shared__ uint4 buf[];          // [WIDTH] = 128 KB
    __shared__ float wsum[(THREADS / 32) * BCH];

    const int g   = blockIdx.x;
    const int tid = threadIdx.x;

    // ---- Load + transpose 8 rows of (weights ‖ neg_weights), fp32 -> fp16 ----
    {
        const float* wb = weights     + (size_t)g * BCH * N_VARS;
        const float* nb = neg_weights + (size_t)g * BCH * N_VARS;
        for (int v = tid; v < N_VARS; v += THREADS) {
            __half2 w01 = __floats2half2_rn(__ldg(wb + v),            __ldg(wb + v + N_VARS));
            __half2 w23 = __floats2half2_rn(__ldg(wb + v + 2*N_VARS), __ldg(wb + v + 3*N_VARS));
            __half2 w45 = __floats2half2_rn(__ldg(wb + v + 4*N_VARS), __ldg(wb + v + 5*N_VARS));
            __half2 w67 = __floats2half2_rn(__ldg(wb + v + 6*N_VARS), __ldg(wb + v + 7*N_VARS));
            buf[v] = make_uint4(h2_as_u32(w01), h2_as_u32(w23), h2_as_u32(w45), h2_as_u32(w67));

            __half2 n01 = __floats2half2_rn(__ldg(nb + v),            __ldg(nb + v + N_VARS));
            __half2 n23 = __floats2half2_rn(__ldg(nb + v + 2*N_VARS), __ldg(nb + v + 3*N_VARS));
            __half2 n45 = __floats2half2_rn(__ldg(nb + v + 4*N_VARS), __ldg(nb + v + 5*N_VARS));
            __half2 n67 = __floats2half2_rn(__ldg(nb + v + 6*N_VARS), __ldg(nb + v + 7*N_VARS));
            buf[v + N_VARS] = make_uint4(h2_as_u32(n01), h2_as_u32(n23), h2_as_u32(n45), h2_as_u32(n67));
        }
    }
    __syncthreads();

    // ---- Stages 0..4: fused (product, sum) layer pairs, in place ----
    #pragma unroll
    for (int p = 0; p < N_PAIRS - 1; ++p) {
        const int4* __restrict__ ft = g_fused + (size_t)p * WIDTH;
        uint4 r[NPT];

        #pragma unroll
        for (int k = 0; k < NPT; ++k) {
            const int4 t = __ldg(&ft[tid + k * THREADS]);
            const uint4 x1 = buf[t.x];
            const uint4 y1 = buf[t.y];
            const uint4 x2 = buf[t.z];
            const uint4 y2 = buf[t.w];
            r[k] = make_uint4(fuse_u(x1.x, y1.x, x2.x, y2.x),
                              fuse_u(x1.y, y1.y, x2.y, y2.y),
                              fuse_u(x1.z, y1.z, x2.z, y2.z),
                              fuse_u(x1.w, y1.w, x2.w, y2.w));
        }
        __syncthreads();
        #pragma unroll
        for (int k = 0; k < NPT; ++k) {
            buf[tid + k * THREADS] = r[k];
        }
        __syncthreads();
    }

    // ---- Stage 5 (layers 10+11): fold into fp32 reduction ----
    float acc[BCH];
    #pragma unroll
    for (int j = 0; j < BCH; ++j) acc[j] = 0.0f;
    {
        const int4* __restrict__ ft = g_fused + (size_t)(N_PAIRS - 1) * WIDTH;
        #pragma unroll
        for (int k = 0; k < NPT; ++k) {
            const int4 t = __ldg(&ft[tid + k * THREADS]);
            const uint4 x1 = buf[t.x];
            const uint4 y1 = buf[t.y];
            const uint4 x2 = buf[t.z];
            const uint4 y2 = buf[t.w];
            const u32 rs[4] = {fuse_u(x1.x, y1.x, x2.x, y2.x),
                               fuse_u(x1.y, y1.y, x2.y, y2.y),
                               fuse_u(x1.z, y1.z, x2.z, y2.z),
                               fuse_u(x1.w, y1.w, x2.w, y2.w)};
            #pragma unroll
            for (int q = 0; q < 4; ++q) {
                float2 f = __half22float2(u32_as_h2(rs[q]));
                acc[2*q + 0] += f.x;
                acc[2*q + 1] += f.y;
            }
        }
    }

    // ---- CTA-wide reduction of 8 fp32 accumulators ----
    #pragma unroll
    for (int o = 16; o > 0; o >>= 1) {
        #pragma unroll
        for (int j = 0; j < BCH; ++j)
            acc[j] += __shfl_xor_sync(0xffffffffu, acc[j], o);
    }
    if ((tid & 31) == 0) {
        #pragma unroll
        for (int j = 0; j < BCH; ++j)
            wsum[(tid >> 5) * BCH + j] = acc[j];
    }
    __syncthreads();

    if (tid < 32) {
        #pragma unroll
        for (int j = 0; j < BCH; ++j) {
            float s = wsum[tid * BCH + j];
            #pragma unroll
            for (int o = 16; o > 0; o >>= 1)
                s += __shfl_xor_sync(0xffffffffu, s, o);
            if (tid == 0) out[g * BCH + j] = s;
        }
    }
}

extern "C" void kernel_launch(void* const* d_in, const int* in_sizes, int n_in,
                              void* d_out, int out_size)
{
    const float* weights     = (const float*)d_in[0];
    const float* neg_weights = (const float*)d_in[1];
    const int2*  children    = (const int2*)d_in[2];
    float* out = (float*)d_out;

    prep_kernel<<<(N_PAIRS * WIDTH) / 256, 256>>>(children);

    const int smem_bytes = WIDTH * sizeof(uint4);    // 128 KB dynamic
    cudaFuncSetAttribute(wmc_kernel, cudaFuncAttributeMaxDynamicSharedMemorySize, smem_bytes);
    wmc_kernel<<<BATCH / BCH, THREADS, smem_bytes>>>(weights, neg_weights, out);
}

// round 7
// speedup vs baseline: 1.0400x; 1.0400x over previous
#include <cuda_runtime.h>
#include <cuda_fp16.h>
#include <cstddef>
#include <cstdint>

#define N_VARS   4096
#define WIDTH    8192
#define N_LAYERS 12
#define BATCH    1024
#define THREADS  1024
#define BCH      8                          // batch rows per CTA (8 halves = 16B/node)
#define NPT      (WIDTH / THREADS)          // 8 nodes per thread
#define NPRE     4                          // table entries prefetched across the barrier
#define N_PAIRS  (N_LAYERS / 2)             // 6 fused product->sum stages

typedef unsigned int u32;

// Fused index tables: for pair p, node i:
//   s = children[2p+1][i];  (A,B) = children[2p][s.x];  (C,D) = children[2p][s.y]
// out[i] = buf[A]*buf[B] + buf[C]*buf[D]
__device__ int4 g_fused[N_PAIRS * WIDTH];

__global__ __launch_bounds__(256) void prep_kernel(const int2* __restrict__ children)
{
    const int idx = blockIdx.x * blockDim.x + threadIdx.x;
    const int p = idx >> 13;          // / WIDTH
    const int i = idx & (WIDTH - 1);
    const int2* ch_even = children + (size_t)(2 * p) * WIDTH;
    const int2 s = __ldg(&children[(size_t)(2 * p + 1) * WIDTH + i]);
    const int2 a = __ldg(&ch_even[s.x]);
    const int2 b = __ldg(&ch_even[s.y]);
    g_fused[idx] = make_int4(a.x, a.y, b.x, b.y);
}

__device__ __forceinline__ u32 h2_as_u32(__half2 h) { u32 r; __builtin_memcpy(&r, &h, 4); return r; }
__device__ __forceinline__ __half2 u32_as_h2(u32 u) { __half2 h; __builtin_memcpy(&h, &u, 4); return h; }

// r = x1*y1 + x2*y2 (half2 lanes)
__device__ __forceinline__ u32 fuse_u(u32 x1, u32 y1, u32 x2, u32 y2) {
    return h2_as_u32(__hfma2(u32_as_h2(x2), u32_as_h2(y2),
                             __hmul2(u32_as_h2(x1), u32_as_h2(y1))));
}

__device__ __forceinline__ uint4 gather_fuse(const uint4* __restrict__ buf, int4 t) {
    const uint4 x1 = buf[t.x];
    const uint4 y1 = buf[t.y];
    const uint4 x2 = buf[t.z];
    const uint4 y2 = buf[t.w];
    return make_uint4(fuse_u(x1.x, y1.x, x2.x, y2.x),
                      fuse_u(x1.y, y1.y, x2.y, y2.y),
                      fuse_u(x1.z, y1.z, x2.z, y2.z),
                      fuse_u(x1.w, y1.w, x2.w, y2.w));
}

// One CTA (32 warps) per group of 8 batch rows; vals node-major as 8 halves
// (uint4) in 128KB SMEM. 6 fused product->sum stages. Software pipeline:
// the first NPRE index-table entries of stage p+1 are loaded during stage p's
// store phase, so their L2 latency drains under the barrier.
__global__ __launch_bounds__(THREADS, 1) void wmc_kernel(
    const float* __restrict__ weights,
    const float* __restrict__ neg_weights,
    float* __restrict__ out)
{
    extern __shared__ uint4 buf[];          // [WIDTH] = 128 KB
    __shared__ float wsum[(THREADS / 32) * BCH];

    const int g   = blockIdx.x;
    const int tid = threadIdx.x;

    // ---- Prefetch stage-0 table (first half) while doing the input load ----
    int4 t_pre[NPRE];
    #pragma unroll
    for (int k = 0; k < NPRE; ++k)
        t_pre[k] = __ldg(&g_fused[tid + k * THREADS]);

    // ---- Load + transpose 8 rows of (weights ‖ neg_weights), fp32 -> fp16 ----
    {
        const float* wb = weights     + (size_t)g * BCH * N_VARS;
        const float* nb = neg_weights + (size_t)g * BCH * N_VARS;
        for (int v = tid; v < N_VARS; v += THREADS) {
            __half2 w01 = __floats2half2_rn(__ldg(wb + v),            __ldg(wb + v + N_VARS));
            __half2 w23 = __floats2half2_rn(__ldg(wb + v + 2*N_VARS), __ldg(wb + v + 3*N_VARS));
            __half2 w45 = __floats2half2_rn(__ldg(wb + v + 4*N_VARS), __ldg(wb + v + 5*N_VARS));
            __half2 w67 = __floats2half2_rn(__ldg(wb + v + 6*N_VARS), __ldg(wb + v + 7*N_VARS));
            buf[v] = make_uint4(h2_as_u32(w01), h2_as_u32(w23), h2_as_u32(w45), h2_as_u32(w67));

            __half2 n01 = __floats2half2_rn(__ldg(nb + v),            __ldg(nb + v + N_VARS));
            __half2 n23 = __floats2half2_rn(__ldg(nb + v + 2*N_VARS), __ldg(nb + v + 3*N_VARS));
            __half2 n45 = __floats2half2_rn(__ldg(nb + v + 4*N_VARS), __ldg(nb + v + 5*N_VARS));
            __half2 n67 = __floats2half2_rn(__ldg(nb + v + 6*N_VARS), __ldg(nb + v + 7*N_VARS));
            buf[v + N_VARS] = make_uint4(h2_as_u32(n01), h2_as_u32(n23), h2_as_u32(n45), h2_as_u32(n67));
        }
    }
    __syncthreads();

    // ---- Stages 0..4: fused (product, sum) layer pairs, in place ----
    #pragma unroll
    for (int p = 0; p < N_PAIRS - 1; ++p) {
        const int4* __restrict__ ft   = g_fused + (size_t)p * WIDTH;
        const int4* __restrict__ ftn  = g_fused + (size_t)(p + 1) * WIDTH;
        uint4 r[NPT];

        // k < NPRE: indices already in registers (prefetched across barrier)
        #pragma unroll
        for (int k = 0; k < NPRE; ++k)
            r[k] = gather_fuse(buf, t_pre[k]);
        // k >= NPRE: load index in-loop (hidden behind the first gathers)
        #pragma unroll
        for (int k = NPRE; k < NPT; ++k)
            r[k] = gather_fuse(buf, __ldg(&ft[tid + k * THREADS]));

        __syncthreads();
        #pragma unroll
        for (int k = 0; k < NPT; ++k)
            buf[tid + k * THREADS] = r[k];
        // prefetch next stage's first-half table: L2 latency drains under bar
        #pragma unroll
        for (int k = 0; k < NPRE; ++k)
            t_pre[k] = __ldg(&ftn[tid + k * THREADS]);
        __syncthreads();
    }

    // ---- Stage 5 (layers 10+11): fold into fp32 reduction ----
    float acc[BCH];
    #pragma unroll
    for (int j = 0; j < BCH; ++j) acc[j] = 0.0f;
    {
        const int4* __restrict__ ft = g_fused + (size_t)(N_PAIRS - 1) * WIDTH;
        #pragma unroll
        for (int k = 0; k < NPT; ++k) {
            const int4 t = (k < NPRE) ? t_pre[k] : __ldg(&ft[tid + k * THREADS]);
            const uint4 rv = gather_fuse(buf, t);
            const u32 rs[4] = {rv.x, rv.y, rv.z, rv.w};
            #pragma unroll
            for (int q = 0; q < 4; ++q) {
                float2 f = __half22float2(u32_as_h2(rs[q]));
                acc[2*q + 0] += f.x;
                acc[2*q + 1] += f.y;
            }
        }
    }

    // ---- CTA-wide reduction of 8 fp32 accumulators ----
    #pragma unroll
    for (int o = 16; o > 0; o >>= 1) {
        #pragma unroll
        for (int j = 0; j < BCH; ++j)
            acc[j] += __shfl_xor_sync(0xffffffffu, acc[j], o);
    }
    if ((tid & 31) == 0) {
        #pragma unroll
        for (int j = 0; j < BCH; ++j)
            wsum[(tid >> 5) * BCH + j] = acc[j];
    }
    __syncthreads();

    if (tid < 32) {
        #pragma unroll
        for (int j = 0; j < BCH; ++j) {
            float s = wsum[tid * BCH + j];
            #pragma unroll
            for (int o = 16; o > 0; o >>= 1)
                s += __shfl_xor_sync(0xffffffffu, s, o);
            if (tid == 0) out[g * BCH + j] = s;
        }
    }
}

extern "C" void kernel_launch(void* const* d_in, const int* in_sizes, int n_in,
                              void* d_out, int out_size)
{
    const float* weights     = (const float*)d_in[0];
    const float* neg_weights = (const float*)d_in[1];
    const int2*  children    = (const int2*)d_in[2];
    float* out = (float*)d_out;

    prep_kernel<<<(N_PAIRS * WIDTH) / 256, 256>>>(children);

    const int smem_bytes = WIDTH * sizeof(uint4);    // 128 KB dynamic
    cudaFuncSetAttribute(wmc_kernel, cudaFuncAttributeMaxDynamicSharedMemorySize, smem_bytes);
    wmc_kernel<<<BATCH / BCH, THREADS, smem_bytes>>>(weights, neg_weights, out);
}